// round 1
// baseline (speedup 1.0000x reference)
#include <cuda_runtime.h>
#include <math.h>

#define BB     32
#define SS     577
#define HID    1408
#define H3     4224
#define NH     16
#define HD     88
#define BH     (BB*NH)      // 512
#define MROWS  (BB*SS)      // 18464
#define SCALEF 0.10660035817780521f   // 88^-0.5

// ---------------- scratch (static device globals; no allocation) -------------
__device__ float g_qkv[(size_t)MROWS * H3];        // 312 MB
__device__ float g_q  [(size_t)BH * SS * HD];      // 104 MB
__device__ float g_k  [(size_t)BH * SS * HD];
__device__ float g_v  [(size_t)BH * SS * HD];
__device__ float g_p  [(size_t)BH * SS * SS];      // 682 MB
__device__ float g_att[(size_t)MROWS * HID];       // 104 MB

// ---------------- generic fp32 GEMM + bias: C[M,N] = A[M,K]@B[K,N] + bias ----
// BM=BN=128, BK=8, 256 threads, 8x8 per thread. N%128==0, K%8==0 assumed;
// M guarded.
__global__ __launch_bounds__(256) void sgemm_bias(
    const float* __restrict__ A, const float* __restrict__ Bm,
    const float* __restrict__ bias, float* __restrict__ C,
    int M, int N, int K)
{
    __shared__ float As[8][128];
    __shared__ float Bs[8][128];

    const int tid  = threadIdx.x;
    const int brow = blockIdx.y * 128;
    const int bcol = blockIdx.x * 128;

    const int trow = (tid >> 4) * 8;   // 0..120
    const int tcol = (tid & 15) * 8;   // 0..120

    const int arow = tid >> 1;          // 0..127
    const int acol = (tid & 1) * 4;     // 0 or 4
    const int brl  = tid >> 5;          // 0..7
    const int bcl  = (tid & 31) * 4;    // 0..124

    float acc[8][8];
#pragma unroll
    for (int i = 0; i < 8; i++)
#pragma unroll
        for (int j = 0; j < 8; j++) acc[i][j] = 0.f;

    for (int k0 = 0; k0 < K; k0 += 8) {
        // load A tile (128x8), transposed into As[k][m]
        float4 a4 = make_float4(0.f, 0.f, 0.f, 0.f);
        int gr = brow + arow;
        if (gr < M)
            a4 = *(const float4*)(A + (size_t)gr * K + k0 + acol);
        As[acol + 0][arow] = a4.x;
        As[acol + 1][arow] = a4.y;
        As[acol + 2][arow] = a4.z;
        As[acol + 3][arow] = a4.w;

        // load B tile (8x128)
        float4 b4 = *(const float4*)(Bm + (size_t)(k0 + brl) * N + bcol + bcl);
        *(float4*)&Bs[brl][bcl] = b4;

        __syncthreads();
#pragma unroll
        for (int kk = 0; kk < 8; kk++) {
            float ar[8], br[8];
#pragma unroll
            for (int i = 0; i < 8; i++) ar[i] = As[kk][trow + i];
#pragma unroll
            for (int j = 0; j < 8; j++) br[j] = Bs[kk][tcol + j];
#pragma unroll
            for (int i = 0; i < 8; i++)
#pragma unroll
                for (int j = 0; j < 8; j++)
                    acc[i][j] += ar[i] * br[j];
        }
        __syncthreads();
    }

#pragma unroll
    for (int i = 0; i < 8; i++) {
        int r = brow + trow + i;
        if (r < M) {
#pragma unroll
            for (int j = 0; j < 8; j++) {
                int c = bcol + tcol + j;
                C[(size_t)r * N + c] = acc[i][j] + bias[c];
            }
        }
    }
}

// ---------------- RoPE + scatter to [bh][s][d] layouts -----------------------
// One thread per (b, s, h, j) rotation pair; also copies the matching V pair.
__global__ __launch_bounds__(256) void rope_scatter(
    const float* __restrict__ qkv,
    float* __restrict__ Q, float* __restrict__ K, float* __restrict__ V)
{
    const long long idx = (long long)blockIdx.x * blockDim.x + threadIdx.x;
    const long long total = (long long)BB * SS * NH * (HD / 2);
    if (idx >= total) return;

    int j = (int)(idx % (HD / 2));            // 0..43
    int h = (int)((idx / (HD / 2)) % NH);
    int s = (int)((idx / ((HD / 2) * NH)) % SS);
    int b = (int)(idx / ((long long)(HD / 2) * NH * SS));

    float c, sn;
    if (s == SS - 1) {          // appended token: idx=-2 -> freqs masked to 0
        c = 1.f; sn = 0.f;
    } else {
        int fx = s % 24;
        int fy = s / 24;
        int jj = (j < 22) ? j : (j - 22);
        int coord = (j < 22) ? (fx + 1) : (fy + 1);
        // inv = 10000^(-jj/22)
        float inv = expf(-(float)jj * 0.41865183508982657f); // ln(1e4)/22
        float arg = (float)coord * inv;
        c  = cosf(arg);
        sn = sinf(arg);
    }

    const float* base = qkv + (size_t)(b * SS + s) * H3 + h * HD;
    float q0 = base[2 * j],        q1 = base[2 * j + 1];
    float k0 = base[HID + 2 * j],  k1 = base[HID + 2 * j + 1];
    float v0 = base[2 * HID + 2 * j], v1 = base[2 * HID + 2 * j + 1];

    size_t o = ((size_t)(b * NH + h) * SS + s) * HD + 2 * j;
    Q[o]     = q0 * c - q1 * sn;
    Q[o + 1] = q0 * sn + q1 * c;
    K[o]     = k0 * c - k1 * sn;
    K[o + 1] = k0 * sn + k1 * c;
    V[o]     = v0;
    V[o + 1] = v1;
}

// ---------------- scores: P[bh][i][j] = SCALE * Q[bh][i]·K[bh][j] ------------
// 64x64 output tile per block, 4x4 per thread, smem transposed [d][row].
__global__ __launch_bounds__(256) void qk_scores(
    const float* __restrict__ Q, const float* __restrict__ K,
    float* __restrict__ P)
{
    __shared__ float Qs[HD][64];
    __shared__ float Ks[HD][64];

    const int bh    = blockIdx.z;
    const int qbase = blockIdx.y * 64;
    const int kbase = blockIdx.x * 64;

    const float* Qb = Q + (size_t)bh * SS * HD;
    const float* Kb = K + (size_t)bh * SS * HD;

    for (int i = threadIdx.x; i < 64 * HD; i += 256) {
        int r = i / HD, d = i % HD;
        Qs[d][r] = (qbase + r < SS) ? Qb[(size_t)(qbase + r) * HD + d] : 0.f;
        Ks[d][r] = (kbase + r < SS) ? Kb[(size_t)(kbase + r) * HD + d] : 0.f;
    }
    __syncthreads();

    const int tx = threadIdx.x & 15;
    const int ty = threadIdx.x >> 4;
    const int r0 = ty * 4;
    const int c0 = tx * 4;

    float acc[4][4];
#pragma unroll
    for (int i = 0; i < 4; i++)
#pragma unroll
        for (int j = 0; j < 4; j++) acc[i][j] = 0.f;

    for (int d = 0; d < HD; d++) {
        float qr[4], kr[4];
#pragma unroll
        for (int i = 0; i < 4; i++) qr[i] = Qs[d][r0 + i];
#pragma unroll
        for (int j = 0; j < 4; j++) kr[j] = Ks[d][c0 + j];
#pragma unroll
        for (int i = 0; i < 4; i++)
#pragma unroll
            for (int j = 0; j < 4; j++)
                acc[i][j] += qr[i] * kr[j];
    }

    float* Pb = P + (size_t)bh * SS * SS;
#pragma unroll
    for (int i = 0; i < 4; i++) {
        int r = qbase + r0 + i;
        if (r < SS) {
#pragma unroll
            for (int j = 0; j < 4; j++) {
                int c = kbase + c0 + j;
                if (c < SS) Pb[(size_t)r * SS + c] = acc[i][j] * SCALEF;
            }
        }
    }
}

// ---------------- softmax: warp per row over 577 elements --------------------
__global__ __launch_bounds__(128) void softmax_rows(float* __restrict__ P)
{
    long long gwarp = ((long long)blockIdx.x * blockDim.x + threadIdx.x) >> 5;
    int lane = threadIdx.x & 31;
    if (gwarp >= (long long)BH * SS) return;

    float* row = P + (size_t)gwarp * SS;

    float m = -1e30f;
    for (int j = lane; j < SS; j += 32) m = fmaxf(m, row[j]);
#pragma unroll
    for (int off = 16; off; off >>= 1)
        m = fmaxf(m, __shfl_xor_sync(0xffffffffu, m, off));

    float sum = 0.f;
    for (int j = lane; j < SS; j += 32) {
        float e = expf(row[j] - m);
        row[j] = e;
        sum += e;
    }
#pragma unroll
    for (int off = 16; off; off >>= 1)
        sum += __shfl_xor_sync(0xffffffffu, sum, off);

    float inv = 1.f / sum;
    for (int j = lane; j < SS; j += 32) row[j] *= inv;
}

// ---------------- PV: O[b, i, h*88+d] = sum_j P[bh][i][j] V[bh][j][d] --------
// Block: (32 q-rows) x 88 cols; 256 threads; each thread 4 rows x 3 cols.
__global__ __launch_bounds__(256) void pv_kernel(
    const float* __restrict__ P, const float* __restrict__ V,
    float* __restrict__ O)
{
    __shared__ float Ps[32][33];
    __shared__ float Vs[32][HD];

    const int bh    = blockIdx.y;
    const int qbase = blockIdx.x * 32;
    const int tx = threadIdx.x & 31;
    const int ty = threadIdx.x >> 5;   // 0..7
    const int r0 = ty * 4;

    const float* Pb = P + (size_t)bh * SS * SS;
    const float* Vb = V + (size_t)bh * SS * HD;

    float acc[4][3];
#pragma unroll
    for (int i = 0; i < 4; i++)
#pragma unroll
        for (int j = 0; j < 3; j++) acc[i][j] = 0.f;

    for (int jt = 0; jt < SS; jt += 32) {
        for (int i = threadIdx.x; i < 32 * 32; i += 256) {
            int r = i >> 5, j = i & 31;
            Ps[r][j] = (qbase + r < SS && jt + j < SS)
                       ? Pb[(size_t)(qbase + r) * SS + jt + j] : 0.f;
        }
        for (int i = threadIdx.x; i < 32 * HD; i += 256) {
            int j = i / HD, d = i % HD;
            Vs[j][d] = (jt + j < SS) ? Vb[(size_t)(jt + j) * HD + d] : 0.f;
        }
        __syncthreads();
#pragma unroll
        for (int j = 0; j < 32; j++) {
            float v0 = Vs[j][tx];
            float v1 = Vs[j][tx + 32];
            float v2 = (tx < 24) ? Vs[j][tx + 64] : 0.f;
#pragma unroll
            for (int i = 0; i < 4; i++) {
                float p = Ps[r0 + i][j];
                acc[i][0] += p * v0;
                acc[i][1] += p * v1;
                acc[i][2] += p * v2;
            }
        }
        __syncthreads();
    }

    const int b = bh >> 4, h = bh & 15;
#pragma unroll
    for (int i = 0; i < 4; i++) {
        int r = qbase + r0 + i;
        if (r < SS) {
            float* o = O + (size_t)(b * SS + r) * HID + h * HD;
            o[tx]      = acc[i][0];
            o[tx + 32] = acc[i][1];
            if (tx < 24) o[tx + 64] = acc[i][2];
        }
    }
}

// ---------------- launch -----------------------------------------------------
extern "C" void kernel_launch(void* const* d_in, const int* in_sizes, int n_in,
                              void* d_out, int out_size)
{
    const float* x     = (const float*)d_in[0];
    const float* w_qkv = (const float*)d_in[1];
    const float* b_qkv = (const float*)d_in[2];
    const float* w_o   = (const float*)d_in[3];
    const float* b_o   = (const float*)d_in[4];
    float* out = (float*)d_out;

    float *qkv, *q, *k, *v, *p, *att;
    cudaGetSymbolAddress((void**)&qkv, g_qkv);
    cudaGetSymbolAddress((void**)&q,   g_q);
    cudaGetSymbolAddress((void**)&k,   g_k);
    cudaGetSymbolAddress((void**)&v,   g_v);
    cudaGetSymbolAddress((void**)&p,   g_p);
    cudaGetSymbolAddress((void**)&att, g_att);

    // 1) QKV projection: [18464,1408] @ [1408,4224] + b
    sgemm_bias<<<dim3(H3 / 128, (MROWS + 127) / 128), 256>>>(
        x, w_qkv, b_qkv, qkv, MROWS, H3, HID);

    // 2) RoPE (q,k) + scatter to [bh][s][d]
    {
        long long total = (long long)BB * SS * NH * (HD / 2);
        int blocks = (int)((total + 255) / 256);
        rope_scatter<<<blocks, 256>>>(qkv, q, k, v);
    }

    // 3) scores = scale * Q K^T  (512 batched [577x88]x[88x577])
    qk_scores<<<dim3((SS + 63) / 64, (SS + 63) / 64, BH), 256>>>(q, k, p);

    // 4) softmax over rows
    {
        long long rows = (long long)BH * SS;
        int blocks = (int)((rows + 3) / 4);   // 4 warps/block
        softmax_rows<<<blocks, 128>>>(p);
    }

    // 5) attn = P @ V, written as [b, s, h*88+d]
    pv_kernel<<<dim3((SS + 31) / 32, BH), 256>>>(p, v, att);

    // 6) output projection: [18464,1408] @ [1408,1408] + b
    sgemm_bias<<<dim3(HID / 128, (MROWS + 127) / 128), 256>>>(
        att, w_o, b_o, out, MROWS, HID, HID);
}

// round 2
// speedup vs baseline: 1.7644x; 1.7644x over previous
#include <cuda_runtime.h>
#include <math.h>
#include <stdint.h>

#define BB     32
#define SS     577
#define HID    1408
#define H3     4224
#define NH     16
#define HD     88
#define BH     (BB*NH)      // 512
#define MROWS  (BB*SS)      // 18464
#define SCALEF 0.10660035817780521f   // 88^-0.5

// ---------------- scratch (static device globals; no allocation) -------------
__device__ float g_qkv[(size_t)MROWS * H3];        // 312 MB
__device__ float g_q  [(size_t)BH * SS * HD];      // 104 MB
__device__ float g_k  [(size_t)BH * SS * HD];
__device__ float g_v  [(size_t)BH * SS * HD];
__device__ float g_p  [(size_t)BH * SS * SS];      // 682 MB
__device__ float g_att[(size_t)MROWS * HID];       // 104 MB

// ---------------- helpers ----------------------------------------------------
__device__ __forceinline__ uint32_t smem_u32(const void* p) {
    return (uint32_t)__cvta_generic_to_shared(p);
}
__device__ __forceinline__ void cp_async16(uint32_t dst, const void* src) {
    asm volatile("cp.async.cg.shared.global [%0], [%1], 16;\n" :: "r"(dst), "l"(src));
}
__device__ __forceinline__ void cp_commit() {
    asm volatile("cp.async.commit_group;\n");
}
__device__ __forceinline__ uint32_t f2tf32(float f) {
    uint32_t u;
    asm("cvt.rna.tf32.f32 %0, %1;\n" : "=r"(u) : "f"(f));
    return u;
}
__device__ __forceinline__ void mma_tf32(float c[4], const uint32_t a[4], const uint32_t b[2]) {
    asm volatile(
        "mma.sync.aligned.m16n8k8.row.col.f32.tf32.tf32.f32 "
        "{%0,%1,%2,%3}, {%4,%5,%6,%7}, {%8,%9}, {%0,%1,%2,%3};\n"
        : "+f"(c[0]), "+f"(c[1]), "+f"(c[2]), "+f"(c[3])
        : "r"(a[0]), "r"(a[1]), "r"(a[2]), "r"(a[3]), "r"(b[0]), "r"(b[1]));
}

// ---------------- tf32 tensor-core GEMM + bias -------------------------------
// C[M,N] = A[M,K] @ B[K,N] + bias.  BM=BN=128, BK=16, 256 threads (8 warps,
// 2x4 grid, 64x32 per warp). N%128==0, K%16==0 required; M guarded.
__global__ __launch_bounds__(256) void tf32_gemm_bias(
    const float* __restrict__ A, const float* __restrict__ Bm,
    const float* __restrict__ bias, float* __restrict__ C,
    int M, int N, int K)
{
    __shared__ float As[2][128][20];   // [m][k], pad 16->20 (conflict-free frags)
    __shared__ float Bs[2][16][136];   // [k][n], pad 128->136

    const int tid  = threadIdx.x;
    const int brow = blockIdx.y * 128;
    const int bcol = blockIdx.x * 128;
    const int wid  = tid >> 5;
    const int lane = tid & 31;
    const int g    = lane >> 2;   // 0..7
    const int t4   = lane & 3;    // 0..3
    const int wm   = (wid >> 2) * 64;   // warp row offset (0/64)
    const int wn   = (wid & 3) * 32;    // warp col offset (0/32/64/96)

    float acc[4][4][4];
#pragma unroll
    for (int mi = 0; mi < 4; mi++)
#pragma unroll
        for (int ni = 0; ni < 4; ni++)
#pragma unroll
            for (int r = 0; r < 4; r++) acc[mi][ni][r] = 0.f;

    const int nk = K / 16;

    // per-thread load coordinates (2 chunks of 16B each for A and B)
#define ISSUE_LOADS(s, k0)                                                     \
    {                                                                          \
        _Pragma("unroll")                                                      \
        for (int t = 0; t < 2; t++) {                                          \
            int chunk = tid + 256 * t;                                         \
            int arow = chunk >> 2;                                             \
            int akc  = (chunk & 3) * 4;                                        \
            uint32_t sa = smem_u32(&As[s][arow][akc]);                         \
            if (brow + arow < M) {                                             \
                cp_async16(sa, A + (size_t)(brow + arow) * K + (k0) + akc);    \
            } else {                                                           \
                *(float4*)&As[s][arow][akc] = make_float4(0.f, 0.f, 0.f, 0.f); \
            }                                                                  \
            int bkr = chunk >> 5;                                              \
            int bnc = (chunk & 31) * 4;                                        \
            cp_async16(smem_u32(&Bs[s][bkr][bnc]),                             \
                       Bm + (size_t)((k0) + bkr) * N + bcol + bnc);            \
        }                                                                      \
        cp_commit();                                                           \
    }

    ISSUE_LOADS(0, 0);

    for (int it = 0; it < nk; ++it) {
        const int s = it & 1;
        if (it + 1 < nk) {
            ISSUE_LOADS((it + 1) & 1, (it + 1) * 16);
            asm volatile("cp.async.wait_group 1;\n");
        } else {
            asm volatile("cp.async.wait_group 0;\n");
        }
        __syncthreads();

#pragma unroll
        for (int ks = 0; ks < 16; ks += 8) {
            uint32_t af[4][4], bf[4][2];
#pragma unroll
            for (int mi = 0; mi < 4; mi++) {
                int r0 = wm + mi * 16 + g;
                af[mi][0] = f2tf32(As[s][r0][ks + t4]);
                af[mi][1] = f2tf32(As[s][r0 + 8][ks + t4]);
                af[mi][2] = f2tf32(As[s][r0][ks + t4 + 4]);
                af[mi][3] = f2tf32(As[s][r0 + 8][ks + t4 + 4]);
            }
#pragma unroll
            for (int ni = 0; ni < 4; ni++) {
                int c0 = wn + ni * 8 + g;
                bf[ni][0] = f2tf32(Bs[s][ks + t4][c0]);
                bf[ni][1] = f2tf32(Bs[s][ks + t4 + 4][c0]);
            }
#pragma unroll
            for (int mi = 0; mi < 4; mi++)
#pragma unroll
                for (int ni = 0; ni < 4; ni++)
                    mma_tf32(acc[mi][ni], af[mi], bf[ni]);
        }
        __syncthreads();
    }

    // epilogue: bias add + store
#pragma unroll
    for (int mi = 0; mi < 4; mi++) {
#pragma unroll
        for (int ni = 0; ni < 4; ni++) {
            int r0 = brow + wm + mi * 16 + g;
            int c0 = bcol + wn + ni * 8 + t4 * 2;
            if (r0 < M) {
                C[(size_t)r0 * N + c0]     = acc[mi][ni][0] + bias[c0];
                C[(size_t)r0 * N + c0 + 1] = acc[mi][ni][1] + bias[c0 + 1];
            }
            if (r0 + 8 < M) {
                C[(size_t)(r0 + 8) * N + c0]     = acc[mi][ni][2] + bias[c0];
                C[(size_t)(r0 + 8) * N + c0 + 1] = acc[mi][ni][3] + bias[c0 + 1];
            }
        }
    }
#undef ISSUE_LOADS
}

// ---------------- RoPE + scatter to [bh][s][d] layouts -----------------------
__global__ __launch_bounds__(256) void rope_scatter(
    const float* __restrict__ qkv,
    float* __restrict__ Q, float* __restrict__ K, float* __restrict__ V)
{
    const long long idx = (long long)blockIdx.x * blockDim.x + threadIdx.x;
    const long long total = (long long)BB * SS * NH * (HD / 2);
    if (idx >= total) return;

    int j = (int)(idx % (HD / 2));            // 0..43
    int h = (int)((idx / (HD / 2)) % NH);
    int s = (int)((idx / ((HD / 2) * NH)) % SS);
    int b = (int)(idx / ((long long)(HD / 2) * NH * SS));

    float c, sn;
    if (s == SS - 1) {          // appended token: idx=-2 -> freqs masked to 0
        c = 1.f; sn = 0.f;
    } else {
        int fx = s % 24;
        int fy = s / 24;
        int jj = (j < 22) ? j : (j - 22);
        int coord = (j < 22) ? (fx + 1) : (fy + 1);
        float inv = expf(-(float)jj * 0.41865183508982657f); // ln(1e4)/22
        float arg = (float)coord * inv;
        c  = cosf(arg);
        sn = sinf(arg);
    }

    const float* base = qkv + (size_t)(b * SS + s) * H3 + h * HD;
    float q0 = base[2 * j],        q1 = base[2 * j + 1];
    float k0 = base[HID + 2 * j],  k1 = base[HID + 2 * j + 1];
    float v0 = base[2 * HID + 2 * j], v1 = base[2 * HID + 2 * j + 1];

    size_t o = ((size_t)(b * NH + h) * SS + s) * HD + 2 * j;
    Q[o]     = q0 * c - q1 * sn;
    Q[o + 1] = q0 * sn + q1 * c;
    K[o]     = k0 * c - k1 * sn;
    K[o + 1] = k0 * sn + k1 * c;
    V[o]     = v0;
    V[o + 1] = v1;
}

// ---------------- scores: P[bh][i][j] = SCALE * Q[bh][i]·K[bh][j] ------------
__global__ __launch_bounds__(256) void qk_scores(
    const float* __restrict__ Q, const float* __restrict__ K,
    float* __restrict__ P)
{
    __shared__ float Qs[HD][64];
    __shared__ float Ks[HD][64];

    const int bh    = blockIdx.z;
    const int qbase = blockIdx.y * 64;
    const int kbase = blockIdx.x * 64;

    const float* Qb = Q + (size_t)bh * SS * HD;
    const float* Kb = K + (size_t)bh * SS * HD;

    for (int i = threadIdx.x; i < 64 * HD; i += 256) {
        int r = i / HD, d = i % HD;
        Qs[d][r] = (qbase + r < SS) ? Qb[(size_t)(qbase + r) * HD + d] : 0.f;
        Ks[d][r] = (kbase + r < SS) ? Kb[(size_t)(kbase + r) * HD + d] : 0.f;
    }
    __syncthreads();

    const int tx = threadIdx.x & 15;
    const int ty = threadIdx.x >> 4;
    const int r0 = ty * 4;
    const int c0 = tx * 4;

    float acc[4][4];
#pragma unroll
    for (int i = 0; i < 4; i++)
#pragma unroll
        for (int j = 0; j < 4; j++) acc[i][j] = 0.f;

    for (int d = 0; d < HD; d++) {
        float qr[4], kr[4];
#pragma unroll
        for (int i = 0; i < 4; i++) qr[i] = Qs[d][r0 + i];
#pragma unroll
        for (int j = 0; j < 4; j++) kr[j] = Ks[d][c0 + j];
#pragma unroll
        for (int i = 0; i < 4; i++)
#pragma unroll
            for (int j = 0; j < 4; j++)
                acc[i][j] += qr[i] * kr[j];
    }

    float* Pb = P + (size_t)bh * SS * SS;
#pragma unroll
    for (int i = 0; i < 4; i++) {
        int r = qbase + r0 + i;
        if (r < SS) {
#pragma unroll
            for (int j = 0; j < 4; j++) {
                int c = kbase + c0 + j;
                if (c < SS) Pb[(size_t)r * SS + c] = acc[i][j] * SCALEF;
            }
        }
    }
}

// ---------------- softmax: warp per row over 577 elements --------------------
__global__ __launch_bounds__(128) void softmax_rows(float* __restrict__ P)
{
    long long gwarp = ((long long)blockIdx.x * blockDim.x + threadIdx.x) >> 5;
    int lane = threadIdx.x & 31;
    if (gwarp >= (long long)BH * SS) return;

    float* row = P + (size_t)gwarp * SS;

    float m = -1e30f;
    for (int j = lane; j < SS; j += 32) m = fmaxf(m, row[j]);
#pragma unroll
    for (int off = 16; off; off >>= 1)
        m = fmaxf(m, __shfl_xor_sync(0xffffffffu, m, off));

    float sum = 0.f;
    for (int j = lane; j < SS; j += 32) {
        float e = expf(row[j] - m);
        row[j] = e;
        sum += e;
    }
#pragma unroll
    for (int off = 16; off; off >>= 1)
        sum += __shfl_xor_sync(0xffffffffu, sum, off);

    float inv = 1.f / sum;
    for (int j = lane; j < SS; j += 32) row[j] *= inv;
}

// ---------------- PV: O[b, i, h*88+d] = sum_j P[bh][i][j] V[bh][j][d] --------
__global__ __launch_bounds__(256) void pv_kernel(
    const float* __restrict__ P, const float* __restrict__ V,
    float* __restrict__ O)
{
    __shared__ float Ps[32][33];
    __shared__ float Vs[32][HD];

    const int bh    = blockIdx.y;
    const int qbase = blockIdx.x * 32;
    const int tx = threadIdx.x & 31;
    const int ty = threadIdx.x >> 5;   // 0..7
    const int r0 = ty * 4;

    const float* Pb = P + (size_t)bh * SS * SS;
    const float* Vb = V + (size_t)bh * SS * HD;

    float acc[4][3];
#pragma unroll
    for (int i = 0; i < 4; i++)
#pragma unroll
        for (int j = 0; j < 3; j++) acc[i][j] = 0.f;

    for (int jt = 0; jt < SS; jt += 32) {
        for (int i = threadIdx.x; i < 32 * 32; i += 256) {
            int r = i >> 5, j = i & 31;
            Ps[r][j] = (qbase + r < SS && jt + j < SS)
                       ? Pb[(size_t)(qbase + r) * SS + jt + j] : 0.f;
        }
        for (int i = threadIdx.x; i < 32 * HD; i += 256) {
            int j = i / HD, d = i % HD;
            Vs[j][d] = (jt + j < SS) ? Vb[(size_t)(jt + j) * HD + d] : 0.f;
        }
        __syncthreads();
#pragma unroll
        for (int j = 0; j < 32; j++) {
            float v0 = Vs[j][tx];
            float v1 = Vs[j][tx + 32];
            float v2 = (tx < 24) ? Vs[j][tx + 64] : 0.f;
#pragma unroll
            for (int i = 0; i < 4; i++) {
                float p = Ps[r0 + i][j];
                acc[i][0] += p * v0;
                acc[i][1] += p * v1;
                acc[i][2] += p * v2;
            }
        }
        __syncthreads();
    }

    const int b = bh >> 4, h = bh & 15;
#pragma unroll
    for (int i = 0; i < 4; i++) {
        int r = qbase + r0 + i;
        if (r < SS) {
            float* o = O + (size_t)(b * SS + r) * HID + h * HD;
            o[tx]      = acc[i][0];
            o[tx + 32] = acc[i][1];
            if (tx < 24) o[tx + 64] = acc[i][2];
        }
    }
}

// ---------------- launch -----------------------------------------------------
extern "C" void kernel_launch(void* const* d_in, const int* in_sizes, int n_in,
                              void* d_out, int out_size)
{
    const float* x     = (const float*)d_in[0];
    const float* w_qkv = (const float*)d_in[1];
    const float* b_qkv = (const float*)d_in[2];
    const float* w_o   = (const float*)d_in[3];
    const float* b_o   = (const float*)d_in[4];
    float* out = (float*)d_out;

    float *qkv, *q, *k, *v, *p, *att;
    cudaGetSymbolAddress((void**)&qkv, g_qkv);
    cudaGetSymbolAddress((void**)&q,   g_q);
    cudaGetSymbolAddress((void**)&k,   g_k);
    cudaGetSymbolAddress((void**)&v,   g_v);
    cudaGetSymbolAddress((void**)&p,   g_p);
    cudaGetSymbolAddress((void**)&att, g_att);

    // 1) QKV projection: [18464,1408] @ [1408,4224] + b  (tf32 tensor cores)
    tf32_gemm_bias<<<dim3(H3 / 128, (MROWS + 127) / 128), 256>>>(
        x, w_qkv, b_qkv, qkv, MROWS, H3, HID);

    // 2) RoPE (q,k) + scatter to [bh][s][d]
    {
        long long total = (long long)BB * SS * NH * (HD / 2);
        int blocks = (int)((total + 255) / 256);
        rope_scatter<<<blocks, 256>>>(qkv, q, k, v);
    }

    // 3) scores = scale * Q K^T  (512 batched [577x88]x[88x577])
    qk_scores<<<dim3((SS + 63) / 64, (SS + 63) / 64, BH), 256>>>(q, k, p);

    // 4) softmax over rows
    {
        long long rows = (long long)BH * SS;
        int blocks = (int)((rows + 3) / 4);   // 4 warps/block
        softmax_rows<<<blocks, 128>>>(p);
    }

    // 5) attn = P @ V, written as [b, s, h*88+d]
    pv_kernel<<<dim3((SS + 31) / 32, BH), 256>>>(p, v, att);

    // 6) output projection: [18464,1408] @ [1408,1408] + b (tf32 tensor cores)
    tf32_gemm_bias<<<dim3(HID / 128, (MROWS + 127) / 128), 256>>>(
        att, w_o, b_o, out, MROWS, HID, HID);
}

// round 3
// speedup vs baseline: 4.2572x; 2.4128x over previous
#include <cuda_runtime.h>
#include <math.h>
#include <stdint.h>

#define BB     32
#define SS     577
#define HID    1408
#define H3     4224
#define NH     16
#define HD     88
#define BH     (BB*NH)      // 512
#define MROWS  (BB*SS)      // 18464
#define SCALEF 0.10660035817780521f   // 88^-0.5

// ---------------- scratch (static device globals; no allocation) -------------
__device__ float g_qkv[(size_t)MROWS * H3];        // 312 MB
__device__ float g_q  [(size_t)BH * SS * HD];      // 104 MB
__device__ float g_k  [(size_t)BH * SS * HD];
__device__ float g_v  [(size_t)BH * SS * HD];
__device__ float g_att[(size_t)MROWS * HID];       // 104 MB

// ---------------- helpers ----------------------------------------------------
__device__ __forceinline__ uint32_t smem_u32(const void* p) {
    return (uint32_t)__cvta_generic_to_shared(p);
}
__device__ __forceinline__ void cp_async16(uint32_t dst, const void* src) {
    asm volatile("cp.async.cg.shared.global [%0], [%1], 16;\n" :: "r"(dst), "l"(src));
}
__device__ __forceinline__ void cp_commit() {
    asm volatile("cp.async.commit_group;\n");
}
__device__ __forceinline__ uint32_t f2tf32(float f) {
    uint32_t u;
    asm("cvt.rna.tf32.f32 %0, %1;\n" : "=r"(u) : "f"(f));
    return u;
}
__device__ __forceinline__ void mma_tf32(float c[4], const uint32_t a[4], const uint32_t b[2]) {
    asm volatile(
        "mma.sync.aligned.m16n8k8.row.col.f32.tf32.tf32.f32 "
        "{%0,%1,%2,%3}, {%4,%5,%6,%7}, {%8,%9}, {%0,%1,%2,%3};\n"
        : "+f"(c[0]), "+f"(c[1]), "+f"(c[2]), "+f"(c[3])
        : "r"(a[0]), "r"(a[1]), "r"(a[2]), "r"(a[3]), "r"(b[0]), "r"(b[1]));
}

// ---------------- tf32 tensor-core GEMM + bias -------------------------------
// C[M,N] = A[M,K] @ B[K,N] + bias.  BM=BN=128, BK=16, 256 threads (8 warps,
// 2x4 grid, 64x32 per warp). N%128==0, K%16==0 required; M guarded.
__global__ __launch_bounds__(256) void tf32_gemm_bias(
    const float* __restrict__ A, const float* __restrict__ Bm,
    const float* __restrict__ bias, float* __restrict__ C,
    int M, int N, int K)
{
    __shared__ float As[2][128][20];
    __shared__ float Bs[2][16][136];

    const int tid  = threadIdx.x;
    const int brow = blockIdx.y * 128;
    const int bcol = blockIdx.x * 128;
    const int wid  = tid >> 5;
    const int lane = tid & 31;
    const int g    = lane >> 2;
    const int t4   = lane & 3;
    const int wm   = (wid >> 2) * 64;
    const int wn   = (wid & 3) * 32;

    float acc[4][4][4];
#pragma unroll
    for (int mi = 0; mi < 4; mi++)
#pragma unroll
        for (int ni = 0; ni < 4; ni++)
#pragma unroll
            for (int r = 0; r < 4; r++) acc[mi][ni][r] = 0.f;

    const int nk = K / 16;

#define ISSUE_LOADS(s, k0)                                                     \
    {                                                                          \
        _Pragma("unroll")                                                      \
        for (int t = 0; t < 2; t++) {                                          \
            int chunk = tid + 256 * t;                                         \
            int arow = chunk >> 2;                                             \
            int akc  = (chunk & 3) * 4;                                        \
            uint32_t sa = smem_u32(&As[s][arow][akc]);                         \
            if (brow + arow < M) {                                             \
                cp_async16(sa, A + (size_t)(brow + arow) * K + (k0) + akc);    \
            } else {                                                           \
                *(float4*)&As[s][arow][akc] = make_float4(0.f, 0.f, 0.f, 0.f); \
            }                                                                  \
            int bkr = chunk >> 5;                                              \
            int bnc = (chunk & 31) * 4;                                        \
            cp_async16(smem_u32(&Bs[s][bkr][bnc]),                             \
                       Bm + (size_t)((k0) + bkr) * N + bcol + bnc);            \
        }                                                                      \
        cp_commit();                                                           \
    }

    ISSUE_LOADS(0, 0);

    for (int it = 0; it < nk; ++it) {
        const int s = it & 1;
        if (it + 1 < nk) {
            ISSUE_LOADS((it + 1) & 1, (it + 1) * 16);
            asm volatile("cp.async.wait_group 1;\n");
        } else {
            asm volatile("cp.async.wait_group 0;\n");
        }
        __syncthreads();

#pragma unroll
        for (int ks = 0; ks < 16; ks += 8) {
            uint32_t af[4][4], bf[4][2];
#pragma unroll
            for (int mi = 0; mi < 4; mi++) {
                int r0 = wm + mi * 16 + g;
                af[mi][0] = f2tf32(As[s][r0][ks + t4]);
                af[mi][1] = f2tf32(As[s][r0 + 8][ks + t4]);
                af[mi][2] = f2tf32(As[s][r0][ks + t4 + 4]);
                af[mi][3] = f2tf32(As[s][r0 + 8][ks + t4 + 4]);
            }
#pragma unroll
            for (int ni = 0; ni < 4; ni++) {
                int c0 = wn + ni * 8 + g;
                bf[ni][0] = f2tf32(Bs[s][ks + t4][c0]);
                bf[ni][1] = f2tf32(Bs[s][ks + t4 + 4][c0]);
            }
#pragma unroll
            for (int mi = 0; mi < 4; mi++)
#pragma unroll
                for (int ni = 0; ni < 4; ni++)
                    mma_tf32(acc[mi][ni], af[mi], bf[ni]);
        }
        __syncthreads();
    }

#pragma unroll
    for (int mi = 0; mi < 4; mi++) {
#pragma unroll
        for (int ni = 0; ni < 4; ni++) {
            int r0 = brow + wm + mi * 16 + g;
            int c0 = bcol + wn + ni * 8 + t4 * 2;
            if (r0 < M) {
                C[(size_t)r0 * N + c0]     = acc[mi][ni][0] + bias[c0];
                C[(size_t)r0 * N + c0 + 1] = acc[mi][ni][1] + bias[c0 + 1];
            }
            if (r0 + 8 < M) {
                C[(size_t)(r0 + 8) * N + c0]     = acc[mi][ni][2] + bias[c0];
                C[(size_t)(r0 + 8) * N + c0 + 1] = acc[mi][ni][3] + bias[c0 + 1];
            }
        }
    }
#undef ISSUE_LOADS
}

// ---------------- RoPE + scatter to [bh][s][d] layouts -----------------------
__global__ __launch_bounds__(256) void rope_scatter(
    const float* __restrict__ qkv,
    float* __restrict__ Q, float* __restrict__ K, float* __restrict__ V)
{
    const long long idx = (long long)blockIdx.x * blockDim.x + threadIdx.x;
    const long long total = (long long)BB * SS * NH * (HD / 2);
    if (idx >= total) return;

    int j = (int)(idx % (HD / 2));
    int h = (int)((idx / (HD / 2)) % NH);
    int s = (int)((idx / ((HD / 2) * NH)) % SS);
    int b = (int)(idx / ((long long)(HD / 2) * NH * SS));

    float c, sn;
    if (s == SS - 1) {
        c = 1.f; sn = 0.f;
    } else {
        int fx = s % 24;
        int fy = s / 24;
        int jj = (j < 22) ? j : (j - 22);
        int coord = (j < 22) ? (fx + 1) : (fy + 1);
        float inv = expf(-(float)jj * 0.41865183508982657f); // ln(1e4)/22
        float arg = (float)coord * inv;
        c  = cosf(arg);
        sn = sinf(arg);
    }

    const float* base = qkv + (size_t)(b * SS + s) * H3 + h * HD;
    float q0 = base[2 * j],        q1 = base[2 * j + 1];
    float k0 = base[HID + 2 * j],  k1 = base[HID + 2 * j + 1];
    float v0 = base[2 * HID + 2 * j], v1 = base[2 * HID + 2 * j + 1];

    size_t o = ((size_t)(b * NH + h) * SS + s) * HD + 2 * j;
    Q[o]     = q0 * c - q1 * sn;
    Q[o + 1] = q0 * sn + q1 * c;
    K[o]     = k0 * c - k1 * sn;
    K[o + 1] = k0 * sn + k1 * c;
    V[o]     = v0;
    V[o + 1] = v1;
}

// ---------------- fused flash attention (tf32 mma) ---------------------------
// Block = (q-tile of 128 rows, bh). 8 warps, warp owns 16 full rows.
// K/V tiles of 64 rows double-buffered in dynamic smem.
#define KSTRIDE 92
#define NT      10          // ceil(577/64)

__global__ __launch_bounds__(256, 1) void flash_attn(
    const float* __restrict__ Q, const float* __restrict__ K,
    const float* __restrict__ V, float* __restrict__ O)
{
    extern __shared__ float sm[];
    float (*Ks)[64][KSTRIDE] = (float (*)[64][KSTRIDE])sm;                 // 2 stages
    float (*Vs)[64][HD]      = (float (*)[64][HD])(sm + 2 * 64 * KSTRIDE);

    const int bh  = blockIdx.y;
    const int q0  = blockIdx.x * 128;
    const int tid = threadIdx.x;
    const int wid = tid >> 5;
    const int lane = tid & 31;
    const int g   = lane >> 2;
    const int t4  = lane & 3;

    const float* Qb = Q + (size_t)bh * SS * HD;
    const float* Kb = K + (size_t)bh * SS * HD;
    const float* Vb = V + (size_t)bh * SS * HD;

    // preload Q fragments (rows r0, r1 = r0+8), tf32
    const int r0 = q0 + wid * 16 + g;
    const int r1 = r0 + 8;
    const int r0c = (r0 < SS) ? r0 : (SS - 1);
    const int r1c = (r1 < SS) ? r1 : (SS - 1);
    uint32_t qf[11][4];
#pragma unroll
    for (int kk = 0; kk < 11; kk++) {
        qf[kk][0] = f2tf32(Qb[(size_t)r0c * HD + kk * 8 + t4]);
        qf[kk][1] = f2tf32(Qb[(size_t)r1c * HD + kk * 8 + t4]);
        qf[kk][2] = f2tf32(Qb[(size_t)r0c * HD + kk * 8 + t4 + 4]);
        qf[kk][3] = f2tf32(Qb[(size_t)r1c * HD + kk * 8 + t4 + 4]);
    }

    float oacc[11][4];
#pragma unroll
    for (int ni = 0; ni < 11; ni++)
#pragma unroll
        for (int r = 0; r < 4; r++) oacc[ni][r] = 0.f;
    float m0 = -1e30f, m1 = -1e30f, l0 = 0.f, l1 = 0.f;

    // tile loader: K 64x88 (stride 92) + V 64x88, rows clamped to SS-1
#define LOAD_TILE(s, j0)                                                   \
    {                                                                      \
        for (int idx = tid; idx < 64 * 22; idx += 256) {                   \
            int row = idx / 22, c4 = (idx % 22) * 4;                       \
            int jr = (j0) + row; jr = (jr < SS) ? jr : (SS - 1);           \
            cp_async16(smem_u32(&Ks[s][row][c4]),                          \
                       Kb + (size_t)jr * HD + c4);                         \
            cp_async16(smem_u32(&Vs[s][row][c4]),                          \
                       Vb + (size_t)jr * HD + c4);                         \
        }                                                                  \
        cp_commit();                                                       \
    }

    LOAD_TILE(0, 0);

    for (int it = 0; it < NT; ++it) {
        const int s = it & 1;
        const int j0 = it * 64;
        if (it + 1 < NT) {
            LOAD_TILE((it + 1) & 1, (it + 1) * 64);
            asm volatile("cp.async.wait_group 1;\n");
        } else {
            asm volatile("cp.async.wait_group 0;\n");
        }
        __syncthreads();

        // ---- S = Q K^T over this tile (16 x 64 per warp) ----
        float sacc[8][4];
#pragma unroll
        for (int ni = 0; ni < 8; ni++)
#pragma unroll
            for (int r = 0; r < 4; r++) sacc[ni][r] = 0.f;

#pragma unroll
        for (int kk = 0; kk < 11; kk++) {
#pragma unroll
            for (int ni = 0; ni < 8; ni++) {
                uint32_t bf[2];
                bf[0] = f2tf32(Ks[s][ni * 8 + g][kk * 8 + t4]);
                bf[1] = f2tf32(Ks[s][ni * 8 + g][kk * 8 + t4 + 4]);
                mma_tf32(sacc[ni], qf[kk], bf);
            }
        }

        // ---- scale + mask ----
#pragma unroll
        for (int ni = 0; ni < 8; ni++)
#pragma unroll
            for (int r = 0; r < 4; r++) sacc[ni][r] *= SCALEF;

        if (j0 + 64 > SS) {
#pragma unroll
            for (int ni = 0; ni < 8; ni++) {
                int c = j0 + ni * 8 + 2 * t4;
                if (c     >= SS) { sacc[ni][0] = -1e30f; sacc[ni][2] = -1e30f; }
                if (c + 1 >= SS) { sacc[ni][1] = -1e30f; sacc[ni][3] = -1e30f; }
            }
        }

        // ---- row stats (quad-local) ----
        float mx0 = -1e30f, mx1 = -1e30f;
#pragma unroll
        for (int ni = 0; ni < 8; ni++) {
            mx0 = fmaxf(mx0, fmaxf(sacc[ni][0], sacc[ni][1]));
            mx1 = fmaxf(mx1, fmaxf(sacc[ni][2], sacc[ni][3]));
        }
#pragma unroll
        for (int off = 1; off < 4; off <<= 1) {
            mx0 = fmaxf(mx0, __shfl_xor_sync(0xffffffffu, mx0, off));
            mx1 = fmaxf(mx1, __shfl_xor_sync(0xffffffffu, mx1, off));
        }

        float m0n = fmaxf(m0, mx0);
        float m1n = fmaxf(m1, mx1);
        float a0 = __expf(m0 - m0n);
        float a1 = __expf(m1 - m1n);

        float rs0 = 0.f, rs1 = 0.f;
#pragma unroll
        for (int ni = 0; ni < 8; ni++) {
            sacc[ni][0] = __expf(sacc[ni][0] - m0n);
            sacc[ni][1] = __expf(sacc[ni][1] - m0n);
            sacc[ni][2] = __expf(sacc[ni][2] - m1n);
            sacc[ni][3] = __expf(sacc[ni][3] - m1n);
            rs0 += sacc[ni][0] + sacc[ni][1];
            rs1 += sacc[ni][2] + sacc[ni][3];
        }
#pragma unroll
        for (int off = 1; off < 4; off <<= 1) {
            rs0 += __shfl_xor_sync(0xffffffffu, rs0, off);
            rs1 += __shfl_xor_sync(0xffffffffu, rs1, off);
        }
        l0 = l0 * a0 + rs0;
        l1 = l1 * a1 + rs1;
        m0 = m0n;
        m1 = m1n;

#pragma unroll
        for (int ni = 0; ni < 11; ni++) {
            oacc[ni][0] *= a0;
            oacc[ni][1] *= a0;
            oacc[ni][2] *= a1;
            oacc[ni][3] *= a1;
        }

        // ---- O += P V : permute P C-layout -> A-layout via quad shfl ----
        const int srcA = 4 * g + (t4 >> 1);
        const int srcB = srcA + 2;
        const bool odd = (t4 & 1);
#pragma unroll
        for (int kk = 0; kk < 8; kk++) {
            float v00 = __shfl_sync(0xffffffffu, sacc[kk][0], srcA);
            float v01 = __shfl_sync(0xffffffffu, sacc[kk][1], srcA);
            float v20 = __shfl_sync(0xffffffffu, sacc[kk][2], srcA);
            float v21 = __shfl_sync(0xffffffffu, sacc[kk][3], srcA);
            float w00 = __shfl_sync(0xffffffffu, sacc[kk][0], srcB);
            float w01 = __shfl_sync(0xffffffffu, sacc[kk][1], srcB);
            float w20 = __shfl_sync(0xffffffffu, sacc[kk][2], srcB);
            float w21 = __shfl_sync(0xffffffffu, sacc[kk][3], srcB);
            uint32_t af[4];
            af[0] = f2tf32(odd ? v01 : v00);   // row g,   col t4
            af[1] = f2tf32(odd ? v21 : v20);   // row g+8, col t4
            af[2] = f2tf32(odd ? w01 : w00);   // row g,   col t4+4
            af[3] = f2tf32(odd ? w21 : w20);   // row g+8, col t4+4
#pragma unroll
            for (int ni = 0; ni < 11; ni++) {
                uint32_t bf[2];
                bf[0] = f2tf32(Vs[s][kk * 8 + t4][ni * 8 + g]);
                bf[1] = f2tf32(Vs[s][kk * 8 + t4 + 4][ni * 8 + g]);
                mma_tf32(oacc[ni], af, bf);
            }
        }
        __syncthreads();
    }

    // ---- normalize + store to [b, s, h*88 + d] ----
    const int b = bh >> 4, h = bh & 15;
    const float il0 = 1.f / l0;
    const float il1 = 1.f / l1;
    if (r0 < SS) {
        float* o = O + (size_t)(b * SS + r0) * HID + h * HD;
#pragma unroll
        for (int ni = 0; ni < 11; ni++) {
            o[ni * 8 + 2 * t4]     = oacc[ni][0] * il0;
            o[ni * 8 + 2 * t4 + 1] = oacc[ni][1] * il0;
        }
    }
    if (r1 < SS) {
        float* o = O + (size_t)(b * SS + r1) * HID + h * HD;
#pragma unroll
        for (int ni = 0; ni < 11; ni++) {
            o[ni * 8 + 2 * t4]     = oacc[ni][2] * il1;
            o[ni * 8 + 2 * t4 + 1] = oacc[ni][3] * il1;
        }
    }
#undef LOAD_TILE
}

// ---------------- launch -----------------------------------------------------
extern "C" void kernel_launch(void* const* d_in, const int* in_sizes, int n_in,
                              void* d_out, int out_size)
{
    const float* x     = (const float*)d_in[0];
    const float* w_qkv = (const float*)d_in[1];
    const float* b_qkv = (const float*)d_in[2];
    const float* w_o   = (const float*)d_in[3];
    const float* b_o   = (const float*)d_in[4];
    float* out = (float*)d_out;

    float *qkv, *q, *k, *v, *att;
    cudaGetSymbolAddress((void**)&qkv, g_qkv);
    cudaGetSymbolAddress((void**)&q,   g_q);
    cudaGetSymbolAddress((void**)&k,   g_k);
    cudaGetSymbolAddress((void**)&v,   g_v);
    cudaGetSymbolAddress((void**)&att, g_att);

    // 1) QKV projection (tf32 tensor cores)
    tf32_gemm_bias<<<dim3(H3 / 128, (MROWS + 127) / 128), 256>>>(
        x, w_qkv, b_qkv, qkv, MROWS, H3, HID);

    // 2) RoPE (q,k) + scatter to [bh][s][d]
    {
        long long total = (long long)BB * SS * NH * (HD / 2);
        int blocks = (int)((total + 255) / 256);
        rope_scatter<<<blocks, 256>>>(qkv, q, k, v);
    }

    // 3) fused flash attention -> att [b, s, h*88+d]
    {
        const int smem_bytes = (2 * 64 * KSTRIDE + 2 * 64 * HD) * 4; // 92160
        cudaFuncSetAttribute(flash_attn,
                             cudaFuncAttributeMaxDynamicSharedMemorySize,
                             smem_bytes);
        flash_attn<<<dim3((SS + 127) / 128, BH), 256, smem_bytes>>>(q, k, v, att);
    }

    // 4) output projection (tf32 tensor cores)
    tf32_gemm_bias<<<dim3(HID / 128, (MROWS + 127) / 128), 256>>>(
        att, w_o, b_o, out, MROWS, HID, HID);
}